// round 15
// baseline (speedup 1.0000x reference)
#include <cuda_runtime.h>
#include <cuda_fp16.h>
#include <cstdint>

// Problem dims
#define KTOT 8192
#define MPAD 2048
#define NPAD 2048
#define MOUT 2000
#define NOUT 2000

// GEMM tiling: 128x128 tiles, 2 CTAs per SM
#define BM 128
#define BN 128
#define BK 64
#define STAGES 3
#define CHUNKS 128
#define TILES_M (MPAD / BM)         // 16
#define TILES_N (NPAD / BN)         // 16
#define NTILES (TILES_M * TILES_N)  // 256
#define TOTALG (NTILES * CHUNKS)    // 32768

#define A_STAGE_BYTES (BM * BK * 2)   // 16 KB
#define B_STAGE_BYTES (BN * BK * 2)   // 16 KB
#define STAGE_BYTES (A_STAGE_BYTES + B_STAGE_BYTES)  // 32 KB
#define SMEM_TOTAL (STAGES * STAGE_BYTES)            // 96 KB

// Fused pre-kernel block partition (contiguous, r13 layout; init replaced by flag reset)
#define NB_W 16384                   // convert_w blocks
#define NB_X 8192                    // convert_x blocks
#define NB_FLAG 2                    // reset g_tflag + g_tdone (512 ints)
#define NB_PRE (NB_W + NB_X + NB_FLAG)

__device__ __half g_Wh[(size_t)MPAD * KTOT];
__device__ __half g_XT[(size_t)NPAD * KTOT];
__device__ int g_tflag[NTILES];      // ticket counter per tile
__device__ int g_tdone[NTILES];      // winner-stored flag per tile

// ---------------- PTX helpers ----------------
__device__ __forceinline__ uint32_t smem_u32(const void* p) {
    uint32_t a;
    asm("{ .reg .u64 t; cvta.to.shared.u64 t, %1; cvt.u32.u64 %0, t; }" : "=r"(a) : "l"(p));
    return a;
}

__device__ __forceinline__ void cp16(uint32_t s, const void* g) {
    asm volatile("cp.async.cg.shared.global [%0], [%1], 16;" :: "r"(s), "l"(g));
}

__device__ __forceinline__ void cp_commit() {
    asm volatile("cp.async.commit_group;" ::: "memory");
}

template <int N>
__device__ __forceinline__ void cp_wait() {
    asm volatile("cp.async.wait_group %0;" :: "n"(N) : "memory");
}

__device__ __forceinline__ void ldsm_x4(uint32_t* r, uint32_t addr) {
    asm volatile("ldmatrix.sync.aligned.m8n8.x4.shared.b16 {%0,%1,%2,%3}, [%4];"
                 : "=r"(r[0]), "=r"(r[1]), "=r"(r[2]), "=r"(r[3]) : "r"(addr));
}

__device__ __forceinline__ void mma16816(float* c, const uint32_t* a, const uint32_t* b) {
    asm volatile(
        "mma.sync.aligned.m16n8k16.row.col.f32.f16.f16.f32 "
        "{%0,%1,%2,%3}, {%4,%5,%6,%7}, {%8,%9}, {%0,%1,%2,%3};"
        : "+f"(c[0]), "+f"(c[1]), "+f"(c[2]), "+f"(c[3])
        : "r"(a[0]), "r"(a[1]), "r"(a[2]), "r"(a[3]), "r"(b[0]), "r"(b[1]));
}

// ---------------- Fused pre-kernel: convert_w | convert_x | flag reset ------
__global__ void __launch_bounds__(256) prep_kernel(const float* __restrict__ W,
                                                   const float* __restrict__ X) {
    const int b = blockIdx.x;

    if (b < NB_W) {
        // ---- convert_w: W [2000,8192] fp32 -> g_Wh [2048,8192] fp16 ----
        size_t t = (size_t)b * 256 + threadIdx.x;
        size_t idx4 = t * 4;
        int row = (int)(idx4 >> 13);
        __half2* ph = reinterpret_cast<__half2*>(&g_Wh[idx4]);
        if (row < MOUT) {
            float4 v = *reinterpret_cast<const float4*>(W + idx4);
            ph[0] = __halves2half2(__float2half_rn(v.x), __float2half_rn(v.y));
            ph[1] = __halves2half2(__float2half_rn(v.z), __float2half_rn(v.w));
        } else {
            __half2 z = __float2half2_rn(0.0f);
            ph[0] = z; ph[1] = z;
        }
    } else if (b < NB_W + NB_X) {
        // ---- convert_x: X [8192,2000] fp32 -> g_XT [2048,8192] fp16 K-major ----
        __shared__ float tile[64][33];
        const int id = b - NB_W;
        const int kb = (id & 127) * 64;
        const int nb = (id >> 7) * 32;
        const int tx = threadIdx.x & 31;
        const int ty = threadIdx.x >> 5;

#pragma unroll
        for (int r = 0; r < 64; r += 8) {
            const int k = kb + ty + r;
            const int n = nb + tx;
            tile[ty + r][tx] = (n < NOUT) ? X[(size_t)k * NOUT + n] : 0.0f;
        }
        __syncthreads();

#pragma unroll
        for (int it = 0; it < 4; it++) {
            const int nloc = ty + it * 8;
            const int n = nb + nloc;
            const int k0 = 2 * tx;
            __half2 v = __halves2half2(__float2half_rn(tile[k0][nloc]),
                                       __float2half_rn(tile[k0 + 1][nloc]));
            *reinterpret_cast<__half2*>(g_XT + (size_t)n * KTOT + kb + k0) = v;
        }
    } else {
        // ---- reset per-tile ticket/done flags (graph-replay safe) ----
        const int i = threadIdx.x;
        if (b == NB_W + NB_X) { if (i < NTILES) g_tflag[i] = 0; }
        else                  { if (i < NTILES) g_tdone[i] = 0; }
    }
}

// ---------------- Persistent GEMM kernel: 2 CTAs/SM, 128x128 tiles ----------
// First CTA to finish a tile's segment stores acc+bias (plain ST), releases
// g_tdone; later contributors wait on g_tdone and atomicAdd their partials.
__global__ void __launch_bounds__(256, 2)
gemm_persist_kernel(const float* __restrict__ bias, float* __restrict__ out) {
    extern __shared__ char sm[];
    const uint32_t sb = smem_u32(sm);
    __shared__ int sTicket;
    const int tid = threadIdx.x;
    const int lane = tid & 31;
    const int wid = tid >> 5;
    const int warp_m = wid & 1;     // 2 warps over M (64 rows each)
    const int warp_n = wid >> 1;    // 4 warps over N (32 cols each)

    const int ncta = gridDim.x;
    const int g0 = (int)(((long long)blockIdx.x * TOTALG) / ncta);
    const int g1 = (int)(((long long)(blockIdx.x + 1) * TOTALG) / ncta);

    const int lrow = tid >> 3;      // 0..31
    const int lcol = tid & 7;
    uint32_t st_off[4];
#pragma unroll
    for (int j = 0; j < 4; j++) {
        uint32_t off = (uint32_t)((lrow + 32 * j) * 128 + lcol * 16);
        st_off[j] = off ^ ((off >> 3) & 0x70);
    }

    auto issue_loads = [&](int g, int s) {
        const int t = g >> 7;
        const int c = g & 127;
        const __half* Ab = g_Wh + ((size_t)(t & 15) << 7) * KTOT + (size_t)c * 64 + lcol * 8;
        const __half* Bb = g_XT + ((size_t)(t >> 4) << 7) * KTOT + (size_t)c * 64 + lcol * 8;
        uint32_t sA = sb + (uint32_t)s * STAGE_BYTES;
        uint32_t sB = sA + A_STAGE_BYTES;
#pragma unroll
        for (int j = 0; j < 4; j++)
            cp16(sA + st_off[j], Ab + (size_t)(lrow + 32 * j) * KTOT);
#pragma unroll
        for (int j = 0; j < 4; j++)
            cp16(sB + st_off[j], Bb + (size_t)(lrow + 32 * j) * KTOT);
    };

    // prologue
    issue_loads(g0, 0);
    cp_commit();
    issue_loads(g0 + 1, 1);
    cp_commit();

    const int fr = lane & 15;
    const int kh = lane >> 4;
    const uint32_t aRow = (uint32_t)((warp_m * 64 + fr) * 128);
    const uint32_t bRow = (uint32_t)((warp_n * 32 + fr) * 128);
    const uint32_t sXor = (uint32_t)((fr & 7) << 4);
    const uint32_t kSel = (uint32_t)(kh * 16);

    const int mw0 = warp_m * 64 + (lane >> 2);
    const int nw0 = warp_n * 32 + (lane & 3) * 2;

    float acc[4][4][4];

    int g = g0;
    int cs = 0;
    int ps = STAGES - 1;
    while (g < g1) {
        const int segEnd = min(g1, ((g >> 7) + 1) << 7);
        const int segTile = g >> 7;

#pragma unroll
        for (int f = 0; f < 4; f++)
#pragma unroll
            for (int j = 0; j < 4; j++)
#pragma unroll
                for (int e = 0; e < 4; e++) acc[f][j][e] = 0.0f;

#pragma unroll 1
        for (; g < segEnd; g++) {
            cp_wait<STAGES - 2>();
            __syncthreads();

            const int pg = g + STAGES - 1;
            if (pg < g1) issue_loads(pg, ps);
            cp_commit();

            const uint32_t sA = sb + (uint32_t)cs * STAGE_BYTES;
            const uint32_t sB = sA + A_STAGE_BYTES;
            const uint32_t aBase = sA + aRow;
            const uint32_t bBase = sB + bRow;

#pragma unroll
            for (int ks = 0; ks < 4; ks++) {
                const uint32_t kc = ((uint32_t)(ks * 32) + kSel) ^ sXor;
                uint32_t af[4][4];
#pragma unroll
                for (int f = 0; f < 4; f++)
                    ldsm_x4(af[f], aBase + (uint32_t)(f * 2048) + kc);
                uint32_t bn[4][2];
#pragma unroll
                for (int t = 0; t < 2; t++) {
                    uint32_t q[4];
                    ldsm_x4(q, bBase + (uint32_t)(t * 2048) + kc);
                    bn[2 * t][0] = q[0];
                    bn[2 * t + 1][0] = q[1];
                    bn[2 * t][1] = q[2];
                    bn[2 * t + 1][1] = q[3];
                }
#pragma unroll
                for (int f = 0; f < 4; f++)
#pragma unroll
                    for (int j = 0; j < 4; j++)
                        mma16816(acc[f][j], af[f], bn[j]);
            }

            if (++cs == STAGES) cs = 0;
            if (++ps == STAGES) ps = 0;
        }

        // ---- segment epilogue: first finisher stores acc+bias, rest atomicAdd ----
        {
            const int m0 = (segTile & 15) << 7;
            const int n0 = (segTile >> 4) << 7;

            __syncthreads();
            if (tid == 0) sTicket = atomicAdd(&g_tflag[segTile], 1);
            __syncthreads();

            if (sTicket == 0) {
                // winner: plain stores with bias
#pragma unroll
                for (int f = 0; f < 4; f++) {
                    int m_a = m0 + mw0 + f * 16;
                    int m_b = m_a + 8;
#pragma unroll
                    for (int j = 0; j < 4; j++) {
                        int n = n0 + nw0 + j * 8;
                        if (n < NOUT) {
                            const float2 bb = *reinterpret_cast<const float2*>(bias + n);
                            if (m_a < MOUT) {
                                float2 v = {acc[f][j][0] + bb.x, acc[f][j][1] + bb.y};
                                *reinterpret_cast<float2*>(out + (size_t)m_a * NOUT + n) = v;
                            }
                            if (m_b < MOUT) {
                                float2 v = {acc[f][j][2] + bb.x, acc[f][j][3] + bb.y};
                                *reinterpret_cast<float2*>(out + (size_t)m_b * NOUT + n) = v;
                            }
                        }
                    }
                }
                __threadfence();          // each thread orders its own stores
                __syncthreads();          // all threads' fences done
                if (tid == 0) atomicExch(&g_tdone[segTile], 1);   // release
            } else {
                if (tid == 0) {
                    while (atomicAdd(&g_tdone[segTile], 0) == 0) {}
                }
                __syncthreads();          // broadcast acquire to all threads
#pragma unroll
                for (int f = 0; f < 4; f++) {
                    int m_a = m0 + mw0 + f * 16;
                    int m_b = m_a + 8;
#pragma unroll
                    for (int j = 0; j < 4; j++) {
                        int n = n0 + nw0 + j * 8;
                        if (n < NOUT) {
                            if (m_a < MOUT) {
                                atomicAdd(out + (size_t)m_a * NOUT + n,     acc[f][j][0]);
                                atomicAdd(out + (size_t)m_a * NOUT + n + 1, acc[f][j][1]);
                            }
                            if (m_b < MOUT) {
                                atomicAdd(out + (size_t)m_b * NOUT + n,     acc[f][j][2]);
                                atomicAdd(out + (size_t)m_b * NOUT + n + 1, acc[f][j][3]);
                            }
                        }
                    }
                }
            }
        }
    }
}

// ---------------- launch ----------------
extern "C" void kernel_launch(void* const* d_in, const int* in_sizes, int n_in,
                              void* d_out, int out_size) {
    const float* W    = (const float*)d_in[0];
    const float* bias = (const float*)d_in[1];
    const float* X    = (const float*)d_in[2];
    float* out        = (float*)d_out;

    (void)in_sizes; (void)n_in; (void)out_size;

    prep_kernel<<<NB_PRE, 256>>>(W, X);

    int nsm = 148;
    cudaDeviceGetAttribute(&nsm, cudaDevAttrMultiProcessorCount, 0);
    cudaFuncSetAttribute(gemm_persist_kernel,
                         cudaFuncAttributeMaxDynamicSharedMemorySize, SMEM_TOTAL);
    gemm_persist_kernel<<<2 * nsm, 256, SMEM_TOTAL>>>(bias, out);
}

// round 16
// speedup vs baseline: 1.2162x; 1.2162x over previous
#include <cuda_runtime.h>
#include <cuda_fp16.h>
#include <cstdint>

// Problem dims
#define KTOT 8192
#define MPAD 2048
#define NPAD 2048
#define MOUT 2000
#define NOUT 2000

// GEMM tiling: 128x128 tiles, 2 CTAs per SM
#define BM 128
#define BN 128
#define BK 64
#define STAGES 3
#define CHUNKS 128
#define TILES_M (MPAD / BM)         // 16
#define TILES_N (NPAD / BN)         // 16
#define NTILES (TILES_M * TILES_N)  // 256
#define TOTALG (NTILES * CHUNKS)    // 32768

#define A_STAGE_BYTES (BM * BK * 2)   // 16 KB
#define B_STAGE_BYTES (BN * BK * 2)   // 16 KB
#define STAGE_BYTES (A_STAGE_BYTES + B_STAGE_BYTES)  // 32 KB
#define SMEM_TOTAL (STAGES * STAGE_BYTES)            // 96 KB

// Fused pre-kernel block partition (contiguous; pad regions rely on static
// zero-init of __device__ globals and are never written)
#define NB_W 16000                   // convert_w blocks: 2000 rows x 8192 /1024
#define NB_X 8064                    // convert_x blocks: 128 k-tiles x 63 n-tiles
#define NB_INIT 3907                 // init blocks (1,000,000 float4 / 256)
#define NB_PRE (NB_W + NB_X + NB_INIT)

__device__ __half g_Wh[(size_t)MPAD * KTOT];   // rows >=2000 stay statically zero
__device__ __half g_XT[(size_t)NPAD * KTOT];   // n >=2000 stays statically zero

// ---------------- PTX helpers ----------------
__device__ __forceinline__ uint32_t smem_u32(const void* p) {
    uint32_t a;
    asm("{ .reg .u64 t; cvta.to.shared.u64 t, %1; cvt.u32.u64 %0, t; }" : "=r"(a) : "l"(p));
    return a;
}

__device__ __forceinline__ void cp16(uint32_t s, const void* g) {
    asm volatile("cp.async.cg.shared.global [%0], [%1], 16;" :: "r"(s), "l"(g));
}

__device__ __forceinline__ void cp_commit() {
    asm volatile("cp.async.commit_group;" ::: "memory");
}

template <int N>
__device__ __forceinline__ void cp_wait() {
    asm volatile("cp.async.wait_group %0;" :: "n"(N) : "memory");
}

__device__ __forceinline__ void ldsm_x4(uint32_t* r, uint32_t addr) {
    asm volatile("ldmatrix.sync.aligned.m8n8.x4.shared.b16 {%0,%1,%2,%3}, [%4];"
                 : "=r"(r[0]), "=r"(r[1]), "=r"(r[2]), "=r"(r[3]) : "r"(addr));
}

__device__ __forceinline__ void mma16816(float* c, const uint32_t* a, const uint32_t* b) {
    asm volatile(
        "mma.sync.aligned.m16n8k16.row.col.f32.f16.f16.f32 "
        "{%0,%1,%2,%3}, {%4,%5,%6,%7}, {%8,%9}, {%0,%1,%2,%3};"
        : "+f"(c[0]), "+f"(c[1]), "+f"(c[2]), "+f"(c[3])
        : "r"(a[0]), "r"(a[1]), "r"(a[2]), "r"(a[3]), "r"(b[0]), "r"(b[1]));
}

// ---------------- Fused pre-kernel: convert_w | convert_x | init_out ------
__global__ void __launch_bounds__(256) prep_kernel(const float* __restrict__ W,
                                                   const float* __restrict__ X,
                                                   const float* __restrict__ bias,
                                                   float* __restrict__ out) {
    const int b = blockIdx.x;

    if (b < NB_W) {
        // ---- convert_w: W [2000,8192] fp32 -> g_Wh rows [0,2000) fp16 ----
        size_t t = (size_t)b * 256 + threadIdx.x;
        size_t idx4 = t * 4;                       // < 2000*8192 always
        __half2* ph = reinterpret_cast<__half2*>(&g_Wh[idx4]);
        float4 v = *reinterpret_cast<const float4*>(W + idx4);
        ph[0] = __halves2half2(__float2half_rn(v.x), __float2half_rn(v.y));
        ph[1] = __halves2half2(__float2half_rn(v.z), __float2half_rn(v.w));
    } else if (b < NB_W + NB_X) {
        // ---- convert_x: X [8192,2000] fp32 -> g_XT [2048,8192] fp16 K-major ----
        __shared__ float tile[64][33];
        const int id = b - NB_W;
        const int kb = (id & 127) * 64;            // 128 k-tiles
        const int nb = (id >> 7) * 32;             // 63 n-tiles (tile 63 all-pad, skipped)
        const int tx = threadIdx.x & 31;
        const int ty = threadIdx.x >> 5;

#pragma unroll
        for (int r = 0; r < 64; r += 8) {
            const int k = kb + ty + r;
            const int n = nb + tx;
            tile[ty + r][tx] = (n < NOUT) ? X[(size_t)k * NOUT + n] : 0.0f;
        }
        __syncthreads();

#pragma unroll
        for (int it = 0; it < 4; it++) {
            const int nloc = ty + it * 8;
            const int n = nb + nloc;
            if (n < NOUT) {
                const int k0 = 2 * tx;
                __half2 v = __halves2half2(__float2half_rn(tile[k0][nloc]),
                                           __float2half_rn(tile[k0 + 1][nloc]));
                *reinterpret_cast<__half2*>(g_XT + (size_t)n * KTOT + kb + k0) = v;
            }
        }
    } else {
        // ---- init_out: out[m][n] = bias[n], float4 granularity ----
        const int q = (b - NB_W - NB_X) * 256 + threadIdx.x;
        if (q < (MOUT * NOUT) / 4) {
            const int row = q / (NOUT / 4);
            const int c4 = q % (NOUT / 4);
            const float4 v = *reinterpret_cast<const float4*>(bias + c4 * 4);
            *reinterpret_cast<float4*>(out + (size_t)row * NOUT + c4 * 4) = v;
        }
    }
}

// ---------------- Persistent GEMM kernel: 2 CTAs/SM, 128x128 tiles ----------
// (byte-identical to the round-13 known-good 185 us kernel)
__global__ void __launch_bounds__(256, 2)
gemm_persist_kernel(float* __restrict__ out) {
    extern __shared__ char sm[];
    const uint32_t sb = smem_u32(sm);
    const int tid = threadIdx.x;
    const int lane = tid & 31;
    const int wid = tid >> 5;
    const int warp_m = wid & 1;     // 2 warps over M (64 rows each)
    const int warp_n = wid >> 1;    // 4 warps over N (32 cols each)

    const int ncta = gridDim.x;
    const int g0 = (int)(((long long)blockIdx.x * TOTALG) / ncta);
    const int g1 = (int)(((long long)(blockIdx.x + 1) * TOTALG) / ncta);

    const int lrow = tid >> 3;      // 0..31
    const int lcol = tid & 7;
    uint32_t st_off[4];
#pragma unroll
    for (int j = 0; j < 4; j++) {
        uint32_t off = (uint32_t)((lrow + 32 * j) * 128 + lcol * 16);
        st_off[j] = off ^ ((off >> 3) & 0x70);
    }

    auto issue_loads = [&](int g, int s) {
        const int t = g >> 7;
        const int c = g & 127;
        const __half* Ab = g_Wh + ((size_t)(t & 15) << 7) * KTOT + (size_t)c * 64 + lcol * 8;
        const __half* Bb = g_XT + ((size_t)(t >> 4) << 7) * KTOT + (size_t)c * 64 + lcol * 8;
        uint32_t sA = sb + (uint32_t)s * STAGE_BYTES;
        uint32_t sB = sA + A_STAGE_BYTES;
#pragma unroll
        for (int j = 0; j < 4; j++)
            cp16(sA + st_off[j], Ab + (size_t)(lrow + 32 * j) * KTOT);
#pragma unroll
        for (int j = 0; j < 4; j++)
            cp16(sB + st_off[j], Bb + (size_t)(lrow + 32 * j) * KTOT);
    };

    // prologue
    issue_loads(g0, 0);
    cp_commit();
    issue_loads(g0 + 1, 1);
    cp_commit();

    const int fr = lane & 15;
    const int kh = lane >> 4;
    const uint32_t aRow = (uint32_t)((warp_m * 64 + fr) * 128);
    const uint32_t bRow = (uint32_t)((warp_n * 32 + fr) * 128);
    const uint32_t sXor = (uint32_t)((fr & 7) << 4);
    const uint32_t kSel = (uint32_t)(kh * 16);

    const int mw0 = warp_m * 64 + (lane >> 2);
    const int nw0 = warp_n * 32 + (lane & 3) * 2;

    float acc[4][4][4];

    int g = g0;
    int cs = 0;
    int ps = STAGES - 1;
    while (g < g1) {
        const int segEnd = min(g1, ((g >> 7) + 1) << 7);
        const int segTile = g >> 7;

#pragma unroll
        for (int f = 0; f < 4; f++)
#pragma unroll
            for (int j = 0; j < 4; j++)
#pragma unroll
                for (int e = 0; e < 4; e++) acc[f][j][e] = 0.0f;

#pragma unroll 1
        for (; g < segEnd; g++) {
            cp_wait<STAGES - 2>();
            __syncthreads();

            const int pg = g + STAGES - 1;
            if (pg < g1) issue_loads(pg, ps);
            cp_commit();

            const uint32_t sA = sb + (uint32_t)cs * STAGE_BYTES;
            const uint32_t sB = sA + A_STAGE_BYTES;
            const uint32_t aBase = sA + aRow;
            const uint32_t bBase = sB + bRow;

#pragma unroll
            for (int ks = 0; ks < 4; ks++) {
                const uint32_t kc = ((uint32_t)(ks * 32) + kSel) ^ sXor;
                uint32_t af[4][4];
#pragma unroll
                for (int f = 0; f < 4; f++)
                    ldsm_x4(af[f], aBase + (uint32_t)(f * 2048) + kc);
                uint32_t bn[4][2];
#pragma unroll
                for (int t = 0; t < 2; t++) {
                    uint32_t q[4];
                    ldsm_x4(q, bBase + (uint32_t)(t * 2048) + kc);
                    bn[2 * t][0] = q[0];
                    bn[2 * t + 1][0] = q[1];
                    bn[2 * t][1] = q[2];
                    bn[2 * t + 1][1] = q[3];
                }
#pragma unroll
                for (int f = 0; f < 4; f++)
#pragma unroll
                    for (int j = 0; j < 4; j++)
                        mma16816(acc[f][j], af[f], bn[j]);
            }

            if (++cs == STAGES) cs = 0;
            if (++ps == STAGES) ps = 0;
        }

        // segment epilogue: RED-add partial tile
        {
            const int m0 = (segTile & 15) << 7;
            const int n0 = (segTile >> 4) << 7;
#pragma unroll
            for (int f = 0; f < 4; f++) {
                int m_a = m0 + mw0 + f * 16;
                int m_b = m_a + 8;
#pragma unroll
                for (int j = 0; j < 4; j++) {
                    int n = n0 + nw0 + j * 8;
                    if (n < NOUT) {
                        if (m_a < MOUT) {
                            atomicAdd(out + (size_t)m_a * NOUT + n,     acc[f][j][0]);
                            atomicAdd(out + (size_t)m_a * NOUT + n + 1, acc[f][j][1]);
                        }
                        if (m_b < MOUT) {
                            atomicAdd(out + (size_t)m_b * NOUT + n,     acc[f][j][2]);
                            atomicAdd(out + (size_t)m_b * NOUT + n + 1, acc[f][j][3]);
                        }
                    }
                }
            }
        }
    }
}

// ---------------- launch ----------------
extern "C" void kernel_launch(void* const* d_in, const int* in_sizes, int n_in,
                              void* d_out, int out_size) {
    const float* W    = (const float*)d_in[0];
    const float* bias = (const float*)d_in[1];
    const float* X    = (const float*)d_in[2];
    float* out        = (float*)d_out;

    (void)in_sizes; (void)n_in; (void)out_size;

    prep_kernel<<<NB_PRE, 256>>>(W, X, bias, out);

    int nsm = 148;
    cudaDeviceGetAttribute(&nsm, cudaDevAttrMultiProcessorCount, 0);
    cudaFuncSetAttribute(gemm_persist_kernel,
                         cudaFuncAttributeMaxDynamicSharedMemorySize, SMEM_TOTAL);
    gemm_persist_kernel<<<2 * nsm, 256, SMEM_TOTAL>>>(out);
}

// round 17
// speedup vs baseline: 1.2194x; 1.0026x over previous
#include <cuda_runtime.h>
#include <cuda_fp16.h>
#include <cstdint>

// Problem dims
#define KTOT 8192
#define MPAD 2048
#define NPAD 2048
#define MOUT 2000
#define NOUT 2000

// GEMM tiling: 128x128 tiles, 2 CTAs per SM
#define BM 128
#define BN 128
#define BK 64
#define STAGES 3
#define CHUNKS 128
#define TILES_M (MPAD / BM)         // 16
#define TILES_N (NPAD / BN)         // 16
#define NTILES (TILES_M * TILES_N)  // 256
#define TOTALG (NTILES * CHUNKS)    // 32768

#define A_STAGE_BYTES (BM * BK * 2)   // 16 KB
#define B_STAGE_BYTES (BN * BK * 2)   // 16 KB
#define STAGE_BYTES (A_STAGE_BYTES + B_STAGE_BYTES)  // 32 KB
#define SMEM_TOTAL (STAGES * STAGE_BYTES)            // 96 KB

// Fused pre-kernel block partition (contiguous; pad regions rely on static
// zero-init of __device__ globals and are never written)
#define NB_W 16000                   // convert_w blocks: 2000 rows x 8192 /1024
#define NB_X 8064                    // convert_x blocks: 128 k-tiles x 63 n-tiles
#define NB_INIT 3907                 // init blocks (1,000,000 float4 / 256)
#define NB_PRE (NB_W + NB_X + NB_INIT)

__device__ __half g_Wh[(size_t)MPAD * KTOT];   // rows >=2000 stay statically zero
__device__ __half g_XT[(size_t)NPAD * KTOT];   // n >=2000 stays statically zero

// ---------------- PTX helpers ----------------
__device__ __forceinline__ uint32_t smem_u32(const void* p) {
    uint32_t a;
    asm("{ .reg .u64 t; cvta.to.shared.u64 t, %1; cvt.u32.u64 %0, t; }" : "=r"(a) : "l"(p));
    return a;
}

__device__ __forceinline__ void cp16(uint32_t s, const void* g) {
    asm volatile("cp.async.cg.shared.global [%0], [%1], 16;" :: "r"(s), "l"(g));
}

__device__ __forceinline__ void cp_commit() {
    asm volatile("cp.async.commit_group;" ::: "memory");
}

template <int N>
__device__ __forceinline__ void cp_wait() {
    asm volatile("cp.async.wait_group %0;" :: "n"(N) : "memory");
}

__device__ __forceinline__ void ldsm_x4(uint32_t* r, uint32_t addr) {
    asm volatile("ldmatrix.sync.aligned.m8n8.x4.shared.b16 {%0,%1,%2,%3}, [%4];"
                 : "=r"(r[0]), "=r"(r[1]), "=r"(r[2]), "=r"(r[3]) : "r"(addr));
}

__device__ __forceinline__ void mma16816(float* c, const uint32_t* a, const uint32_t* b) {
    asm volatile(
        "mma.sync.aligned.m16n8k16.row.col.f32.f16.f16.f32 "
        "{%0,%1,%2,%3}, {%4,%5,%6,%7}, {%8,%9}, {%0,%1,%2,%3};"
        : "+f"(c[0]), "+f"(c[1]), "+f"(c[2]), "+f"(c[3])
        : "r"(a[0]), "r"(a[1]), "r"(a[2]), "r"(a[3]), "r"(b[0]), "r"(b[1]));
}

// vector RED: single red.global.v2.f32.add (sm_90+)
__device__ __forceinline__ void red_add_f32x2(float* p, float x, float y) {
    asm volatile("red.global.v2.f32.add [%0], {%1, %2};"
                 :: "l"(p), "f"(x), "f"(y) : "memory");
}

// ---------------- Fused pre-kernel: convert_w | convert_x | init_out ------
__global__ void __launch_bounds__(256) prep_kernel(const float* __restrict__ W,
                                                   const float* __restrict__ X,
                                                   const float* __restrict__ bias,
                                                   float* __restrict__ out) {
    const int b = blockIdx.x;

    if (b < NB_W) {
        // ---- convert_w: W [2000,8192] fp32 -> g_Wh rows [0,2000) fp16 ----
        size_t t = (size_t)b * 256 + threadIdx.x;
        size_t idx4 = t * 4;                       // < 2000*8192 always
        __half2* ph = reinterpret_cast<__half2*>(&g_Wh[idx4]);
        float4 v = *reinterpret_cast<const float4*>(W + idx4);
        ph[0] = __halves2half2(__float2half_rn(v.x), __float2half_rn(v.y));
        ph[1] = __halves2half2(__float2half_rn(v.z), __float2half_rn(v.w));
    } else if (b < NB_W + NB_X) {
        // ---- convert_x: X [8192,2000] fp32 -> g_XT [2048,8192] fp16 K-major ----
        __shared__ float tile[64][33];
        const int id = b - NB_W;
        const int kb = (id & 127) * 64;            // 128 k-tiles
        const int nb = (id >> 7) * 32;             // 63 n-tiles (tile 63 all-pad, skipped)
        const int tx = threadIdx.x & 31;
        const int ty = threadIdx.x >> 5;

#pragma unroll
        for (int r = 0; r < 64; r += 8) {
            const int k = kb + ty + r;
            const int n = nb + tx;
            tile[ty + r][tx] = (n < NOUT) ? X[(size_t)k * NOUT + n] : 0.0f;
        }
        __syncthreads();

#pragma unroll
        for (int it = 0; it < 4; it++) {
            const int nloc = ty + it * 8;
            const int n = nb + nloc;
            if (n < NOUT) {
                const int k0 = 2 * tx;
                __half2 v = __halves2half2(__float2half_rn(tile[k0][nloc]),
                                           __float2half_rn(tile[k0 + 1][nloc]));
                *reinterpret_cast<__half2*>(g_XT + (size_t)n * KTOT + kb + k0) = v;
            }
        }
    } else {
        // ---- init_out: out[m][n] = bias[n], float4 granularity ----
        const int q = (b - NB_W - NB_X) * 256 + threadIdx.x;
        if (q < (MOUT * NOUT) / 4) {
            const int row = q / (NOUT / 4);
            const int c4 = q % (NOUT / 4);
            const float4 v = *reinterpret_cast<const float4*>(bias + c4 * 4);
            *reinterpret_cast<float4*>(out + (size_t)row * NOUT + c4 * 4) = v;
        }
    }
}

// ---------------- Persistent GEMM kernel: 2 CTAs/SM, 128x128 tiles ----------
// Mainloop byte-identical to the known-good 185 us kernel; epilogue uses
// vector red.global.v2.f32 (half the atomic op count).
__global__ void __launch_bounds__(256, 2)
gemm_persist_kernel(float* __restrict__ out) {
    extern __shared__ char sm[];
    const uint32_t sb = smem_u32(sm);
    const int tid = threadIdx.x;
    const int lane = tid & 31;
    const int wid = tid >> 5;
    const int warp_m = wid & 1;     // 2 warps over M (64 rows each)
    const int warp_n = wid >> 1;    // 4 warps over N (32 cols each)

    const int ncta = gridDim.x;
    const int g0 = (int)(((long long)blockIdx.x * TOTALG) / ncta);
    const int g1 = (int)(((long long)(blockIdx.x + 1) * TOTALG) / ncta);

    const int lrow = tid >> 3;      // 0..31
    const int lcol = tid & 7;
    uint32_t st_off[4];
#pragma unroll
    for (int j = 0; j < 4; j++) {
        uint32_t off = (uint32_t)((lrow + 32 * j) * 128 + lcol * 16);
        st_off[j] = off ^ ((off >> 3) & 0x70);
    }

    auto issue_loads = [&](int g, int s) {
        const int t = g >> 7;
        const int c = g & 127;
        const __half* Ab = g_Wh + ((size_t)(t & 15) << 7) * KTOT + (size_t)c * 64 + lcol * 8;
        const __half* Bb = g_XT + ((size_t)(t >> 4) << 7) * KTOT + (size_t)c * 64 + lcol * 8;
        uint32_t sA = sb + (uint32_t)s * STAGE_BYTES;
        uint32_t sB = sA + A_STAGE_BYTES;
#pragma unroll
        for (int j = 0; j < 4; j++)
            cp16(sA + st_off[j], Ab + (size_t)(lrow + 32 * j) * KTOT);
#pragma unroll
        for (int j = 0; j < 4; j++)
            cp16(sB + st_off[j], Bb + (size_t)(lrow + 32 * j) * KTOT);
    };

    // prologue
    issue_loads(g0, 0);
    cp_commit();
    issue_loads(g0 + 1, 1);
    cp_commit();

    const int fr = lane & 15;
    const int kh = lane >> 4;
    const uint32_t aRow = (uint32_t)((warp_m * 64 + fr) * 128);
    const uint32_t bRow = (uint32_t)((warp_n * 32 + fr) * 128);
    const uint32_t sXor = (uint32_t)((fr & 7) << 4);
    const uint32_t kSel = (uint32_t)(kh * 16);

    const int mw0 = warp_m * 64 + (lane >> 2);
    const int nw0 = warp_n * 32 + (lane & 3) * 2;

    float acc[4][4][4];

    int g = g0;
    int cs = 0;
    int ps = STAGES - 1;
    while (g < g1) {
        const int segEnd = min(g1, ((g >> 7) + 1) << 7);
        const int segTile = g >> 7;

#pragma unroll
        for (int f = 0; f < 4; f++)
#pragma unroll
            for (int j = 0; j < 4; j++)
#pragma unroll
                for (int e = 0; e < 4; e++) acc[f][j][e] = 0.0f;

#pragma unroll 1
        for (; g < segEnd; g++) {
            cp_wait<STAGES - 2>();
            __syncthreads();

            const int pg = g + STAGES - 1;
            if (pg < g1) issue_loads(pg, ps);
            cp_commit();

            const uint32_t sA = sb + (uint32_t)cs * STAGE_BYTES;
            const uint32_t sB = sA + A_STAGE_BYTES;
            const uint32_t aBase = sA + aRow;
            const uint32_t bBase = sB + bRow;

#pragma unroll
            for (int ks = 0; ks < 4; ks++) {
                const uint32_t kc = ((uint32_t)(ks * 32) + kSel) ^ sXor;
                uint32_t af[4][4];
#pragma unroll
                for (int f = 0; f < 4; f++)
                    ldsm_x4(af[f], aBase + (uint32_t)(f * 2048) + kc);
                uint32_t bn[4][2];
#pragma unroll
                for (int t = 0; t < 2; t++) {
                    uint32_t q[4];
                    ldsm_x4(q, bBase + (uint32_t)(t * 2048) + kc);
                    bn[2 * t][0] = q[0];
                    bn[2 * t + 1][0] = q[1];
                    bn[2 * t][1] = q[2];
                    bn[2 * t + 1][1] = q[3];
                }
#pragma unroll
                for (int f = 0; f < 4; f++)
#pragma unroll
                    for (int j = 0; j < 4; j++)
                        mma16816(acc[f][j], af[f], bn[j]);
            }

            if (++cs == STAGES) cs = 0;
            if (++ps == STAGES) ps = 0;
        }

        // segment epilogue: vector RED-add partial tile (n even, out 256B-aligned)
        {
            const int m0 = (segTile & 15) << 7;
            const int n0 = (segTile >> 4) << 7;
#pragma unroll
            for (int f = 0; f < 4; f++) {
                int m_a = m0 + mw0 + f * 16;
                int m_b = m_a + 8;
#pragma unroll
                for (int j = 0; j < 4; j++) {
                    int n = n0 + nw0 + j * 8;
                    if (n < NOUT) {
                        if (m_a < MOUT)
                            red_add_f32x2(out + (size_t)m_a * NOUT + n,
                                          acc[f][j][0], acc[f][j][1]);
                        if (m_b < MOUT)
                            red_add_f32x2(out + (size_t)m_b * NOUT + n,
                                          acc[f][j][2], acc[f][j][3]);
                    }
                }
            }
        }
    }
}

// ---------------- launch ----------------
extern "C" void kernel_launch(void* const* d_in, const int* in_sizes, int n_in,
                              void* d_out, int out_size) {
    const float* W    = (const float*)d_in[0];
    const float* bias = (const float*)d_in[1];
    const float* X    = (const float*)d_in[2];
    float* out        = (float*)d_out;

    (void)in_sizes; (void)n_in; (void)out_size;

    prep_kernel<<<NB_PRE, 256>>>(W, X, bias, out);

    int nsm = 148;
    cudaDeviceGetAttribute(&nsm, cudaDevAttrMultiProcessorCount, 0);
    cudaFuncSetAttribute(gemm_persist_kernel,
                         cudaFuncAttributeMaxDynamicSharedMemorySize, SMEM_TOTAL);
    gemm_persist_kernel<<<2 * nsm, 256, SMEM_TOTAL>>>(out);
}